// round 15
// baseline (speedup 1.0000x reference)
#include <cuda_runtime.h>
#include <cuda_fp16.h>
#include <math.h>

// ---------------------------------------------------------------------------
// Bidirectional LSTM: T=512, B=32, I=1024, H=1024.
// Round 15: halve per-CTA recurrence work: 256 CTAs (2 dirs x 128 slices of
// 8 units), 8 warps = 2 m16-tiles x 4 k-quarters (kc = 4i + kq), W in regs
// (16 chunks/warp), smem 84.5KB -> guaranteed 2 CTAs/SM co-residency.
// W prologue staged through the Hs region. Barrier/tail/GEMM = exact R10.
// ---------------------------------------------------------------------------

namespace {
constexpr int T = 512;
constexpr int B = 32;
constexpr int I = 1024;
constexpr int H = 1024;
constexpr int G4 = 4 * H;          // 4096
constexpr int N_ALL = 2 * G4;      // 8192
constexpr int OUT_COLS = 2 * H;    // 2048
constexpr int M_ALL = T * B;       // 16384
constexpr long long OUT_MAIN = (long long)T * B * OUT_COLS;

constexpr int CTAS = 256;          // 2 dirs x 128 slices of 8 units
constexpr int THREADS = 256;
constexpr int CTAS_PER_DIR = 128;

constexpr int HS_PITCH = 1032;
constexpr int SMEM_HS = 32 * HS_PITCH * 2;          // 66048 (also W prologue)
constexpr int SMEM_GS = SMEM_HS;                    // Gs after Hs
constexpr int SMEM_BYTES = SMEM_GS + 4 * 32 * 36 * 4;   // 84480 -> 2 CTAs/SM

constexpr int KC = 64;
constexpr int M16 = M_ALL / 16;    // 1024
constexpr int N16 = N_ALL / 16;    // 512

// GEMM: 3 stages x (A 1024 + B 256) uint4 (exact R10)
constexpr int GEMM_SMEM = 3 * (1024 + 256) * 16;    // 61440
}

__device__ __half g_xg[2LL * M_ALL * G4];
__device__ float g_c[2 * B * H];
__device__ __half g_hstage[2][2][B][H];
__device__ unsigned g_bar[2];
__device__ uint4 g_xa[(long long)M16 * KC * 32];
__device__ uint4 g_wb[(long long)N16 * KC * 32];

__device__ __forceinline__ void mma_fp16(float* d, const uint4& a,
                                         unsigned b0, unsigned b1) {
    asm volatile(
        "mma.sync.aligned.m16n8k16.row.col.f32.f16.f16.f32 "
        "{%0,%1,%2,%3}, {%4,%5,%6,%7}, {%8,%9}, {%0,%1,%2,%3};"
        : "+f"(d[0]), "+f"(d[1]), "+f"(d[2]), "+f"(d[3])
        : "r"(a.x), "r"(a.y), "r"(a.z), "r"(a.w), "r"(b0), "r"(b1));
}

__device__ __forceinline__ float sig_(float x) {
    return 1.f / (1.f + __expf(-x));
}
__device__ __forceinline__ float tanh_(float x) {
    float t = __expf(-2.f * fabsf(x));
    float r = (1.f - t) / (1.f + t);
    return x < 0.f ? -r : r;
}

__device__ __forceinline__ void red_release_add(unsigned* p) {
    asm volatile("red.release.gpu.global.add.u32 [%0], %1;"
                 :: "l"(p), "r"(1u) : "memory");
}
__device__ __forceinline__ unsigned ld_acquire(const unsigned* p) {
    unsigned v;
    asm volatile("ld.acquire.gpu.global.u32 %0, [%1];"
                 : "=r"(v) : "l"(p) : "memory");
    return v;
}

#define CP_ASYNC16(smem_u32, gptr) \
    asm volatile("cp.async.cg.shared.global [%0], [%1], 16;" \
                 :: "r"(smem_u32), "l"(gptr))
#define CP_COMMIT() asm volatile("cp.async.commit_group;")
#define CP_WAIT1() asm volatile("cp.async.wait_group 1;")
#define CP_WAIT0() asm volatile("cp.async.wait_group 0;")

// ---------------------------------------------------------------------------
__global__ void init_kernel(const float* __restrict__ h0f,
                            const float* __restrict__ h0b) {
    int i = blockIdx.x * blockDim.x + threadIdx.x;
    if (i == 0) { g_bar[0] = 0; g_bar[1] = 0; }
    if (i < B * H) {
        int b = i >> 10;
        int k = i & 1023;
        g_hstage[0][0][b][k] = __float2half(h0f[i]);
        g_hstage[0][1][b][k] = __float2half(h0b[i]);
    }
}

// ---------------------------------------------------------------------------
__global__ void prepack_x(const float* __restrict__ x) {
    int idx = blockIdx.x * blockDim.x + threadIdx.x;
    if (idx >= M16 * KC * 32) return;
    int lane = idx & 31;
    int kc = (idx >> 5) & 63;
    int m16 = idx >> 11;
    int r = lane >> 2;
    int t4 = lane & 3;
    int m0 = m16 * 16;
    int k0 = kc * 16 + 2 * t4;
    float2 f0 = *(const float2*)&x[(size_t)(m0 + r) * I + k0];
    float2 f1 = *(const float2*)&x[(size_t)(m0 + r + 8) * I + k0];
    float2 f2 = *(const float2*)&x[(size_t)(m0 + r) * I + k0 + 8];
    float2 f3 = *(const float2*)&x[(size_t)(m0 + r + 8) * I + k0 + 8];
    __half2 h0 = __float22half2_rn(f0);
    __half2 h1 = __float22half2_rn(f1);
    __half2 h2 = __float22half2_rn(f2);
    __half2 h3 = __float22half2_rn(f3);
    uint4 v;
    v.x = *(unsigned*)&h0; v.y = *(unsigned*)&h1;
    v.z = *(unsigned*)&h2; v.w = *(unsigned*)&h3;
    g_xa[idx] = v;
}

__global__ void prepack_w(const float* __restrict__ Wf,
                          const float* __restrict__ Wb) {
    int idx = blockIdx.x * blockDim.x + threadIdx.x;
    if (idx >= N16 * KC * 32) return;
    int lane = idx & 31;
    int kc = (idx >> 5) & 63;
    int n16 = idx >> 11;
    int n = n16 * 16;
    const float* W = (n >= G4) ? Wb : Wf;
    int g = n & (G4 - 1);
    int r = lane >> 2;
    int t4 = lane & 3;
    int k0 = kc * 16 + 2 * t4;
    float2 f0 = *(const float2*)&W[(size_t)(g + r) * H + k0];
    float2 f1 = *(const float2*)&W[(size_t)(g + r) * H + k0 + 8];
    float2 f2 = *(const float2*)&W[(size_t)(g + r + 8) * H + k0];
    float2 f3 = *(const float2*)&W[(size_t)(g + r + 8) * H + k0 + 8];
    __half2 h0 = __float22half2_rn(f0);
    __half2 h1 = __float22half2_rn(f1);
    __half2 h2 = __float22half2_rn(f2);
    __half2 h3 = __float22half2_rn(f3);
    uint4 v;
    v.x = *(unsigned*)&h0; v.y = *(unsigned*)&h1;
    v.z = *(unsigned*)&h2; v.w = *(unsigned*)&h3;
    g_wb[idx] = v;
}

// ---------------------------------------------------------------------------
// xg GEMM (exact R10): CTA tile 256x64, 128 threads, 4 warps m128n32,
// BK=32, 3-stage cp.async, 2 CTAs/SM. grid = (128, 64).
// ---------------------------------------------------------------------------
__global__ __launch_bounds__(128, 2)
void xg_gemm_hmma(const float* __restrict__ bihf, const float* __restrict__ bhhf,
                  const float* __restrict__ bihb, const float* __restrict__ bhhb) {
    extern __shared__ char gsm[];
    uint4* sA = (uint4*)gsm;                    // 3 x 1024
    uint4* sB = (uint4*)(gsm + 3 * 16384);      // 3 x 256

    const int tid = threadIdx.x;
    const int m0 = blockIdx.y * 256;
    const int n0 = blockIdx.x * 64;
    const int m16g0 = m0 >> 4;
    const int n16g0 = n0 >> 4;

    const int warp = tid >> 5;
    const int lane = tid & 31;
    const int wm = warp >> 1;
    const int wn = warp & 1;
    const int gID = lane >> 2;
    const int t4 = lane & 3;

    float acc[8][4][4];
#pragma unroll
    for (int i = 0; i < 8; i++)
#pragma unroll
        for (int j = 0; j < 4; j++)
#pragma unroll
            for (int q = 0; q < 4; q++) acc[i][j][q] = 0.f;

    int a_16l[8], a_kcl[8], a_lane[8];
#pragma unroll
    for (int j = 0; j < 8; j++) {
        int i = tid + j * 128;
        a_16l[j] = i >> 6;
        a_kcl[j] = (i >> 5) & 1;
        a_lane[j] = i & 31;
    }
    int b_16l[2], b_kcl[2], b_lane[2];
#pragma unroll
    for (int j = 0; j < 2; j++) {
        int i = tid + j * 128;
        b_16l[j] = i >> 6;
        b_kcl[j] = (i >> 5) & 1;
        b_lane[j] = i & 31;
    }

    auto issue_stage = [&](int buf, int ks) {
#pragma unroll
        for (int j = 0; j < 8; j++) {
            const uint4* src = g_xa +
                ((size_t)(m16g0 + a_16l[j]) * KC + ks * 2 + a_kcl[j]) * 32 + a_lane[j];
            unsigned dst = (unsigned)__cvta_generic_to_shared(
                &sA[buf * 1024 + (a_16l[j] * 2 + a_kcl[j]) * 32 + a_lane[j]]);
            CP_ASYNC16(dst, src);
        }
#pragma unroll
        for (int j = 0; j < 2; j++) {
            const uint4* src = g_wb +
                ((size_t)(n16g0 + b_16l[j]) * KC + ks * 2 + b_kcl[j]) * 32 + b_lane[j];
            unsigned dst = (unsigned)__cvta_generic_to_shared(
                &sB[buf * 256 + (b_16l[j] * 2 + b_kcl[j]) * 32 + b_lane[j]]);
            CP_ASYNC16(dst, src);
        }
        CP_COMMIT();
    };

    issue_stage(0, 0);
    issue_stage(1, 1);

    int cur = 0;
    for (int ks = 0; ks < 32; ks++) {
        if (ks < 31) { CP_WAIT1(); } else { CP_WAIT0(); }
        __syncthreads();
        if (ks + 2 < 32) {
            int nbuf = cur + 2;
            if (nbuf >= 3) nbuf -= 3;
            issue_stage(nbuf, ks + 2);
        }

#pragma unroll
        for (int kcl = 0; kcl < 2; kcl++) {
            uint4 b[2];
#pragma unroll
            for (int j = 0; j < 2; j++)
                b[j] = sB[cur * 256 + ((wn * 2 + j) * 2 + kcl) * 32 + lane];
#pragma unroll
            for (int i = 0; i < 8; i++) {
                uint4 a = sA[cur * 1024 + ((wm * 8 + i) * 2 + kcl) * 32 + lane];
#pragma unroll
                for (int j = 0; j < 2; j++) {
                    mma_fp16(acc[i][2 * j],     a, b[j].x, b[j].y);
                    mma_fp16(acc[i][2 * j + 1], a, b[j].z, b[j].w);
                }
            }
        }
        cur++;
        if (cur == 3) cur = 0;
    }

    const int d = n0 >> 12;
    const float* bih = d ? bihb : bihf;
    const float* bhh = d ? bhhb : bhhf;
    __half* outd = g_xg + (size_t)d * M_ALL * G4;

#pragma unroll
    for (int jj = 0; jj < 4; jj++) {
        int col = n0 + wn * 32 + jj * 8 + 2 * t4;
        int g = col & (G4 - 1);
        float bx = bih[g] + bhh[g];
        float by = bih[g + 1] + bhh[g + 1];
#pragma unroll
        for (int i = 0; i < 8; i++) {
            int row0 = m0 + wm * 128 + i * 16 + gID;
            __half2 v0 = __floats2half2_rn(acc[i][jj][0] + bx, acc[i][jj][1] + by);
            __half2 v1 = __floats2half2_rn(acc[i][jj][2] + bx, acc[i][jj][3] + by);
            *(__half2*)&outd[(size_t)row0 * G4 + g] = v0;
            *(__half2*)&outd[(size_t)(row0 + 8) * G4 + g] = v1;
        }
    }
}

// ---------------------------------------------------------------------------
// Persistent recurrence kernel: 256 CTAs, 256 threads, 2 CTAs/SM.
// CTA = (d, s) with 8 units, gate rows row = gate*8 + u (32 rows, 2 m16).
// Warp = (mh = m16 tile 0..1, kq = k-quarter 0..3); kc = 4i + kq, i<16.
// W prologue staged through the Hs smem region, then held in registers.
// ---------------------------------------------------------------------------
__global__ __launch_bounds__(THREADS, 2)
void lstm_persistent(const float* __restrict__ Whhf,
                     const float* __restrict__ Whhb,
                     const float* __restrict__ c0f,
                     const float* __restrict__ c0b,
                     float* __restrict__ out) {
    extern __shared__ char smem[];
    __half* Hs = (__half*)smem;
    uint4*  Wstage = (uint4*)smem;                   // aliases Hs, prologue only
    float*  Gs = (float*)(smem + SMEM_GS);           // [4][32][36]

    const int tid = threadIdx.x;
    const int d = blockIdx.x >> 7;
    const int s = blockIdx.x & 127;
    const int j0 = s * 8;
    const float* Whh = d ? Whhb : Whhf;

    // ---- prologue: pack W slice (32 rows x 1024 k) into fragment layout ----
    // entries: [mt 0..1][kc 0..63][lane 0..31]; 4096 uint4 = 64KB in Hs region
    for (int s0 = tid; s0 < 2 * 64 * 32; s0 += THREADS) {
        int l  = s0 & 31;
        int kc = (s0 >> 5) & 63;
        int mt = s0 >> 11;
        int r  = l >> 2;
        int t4 = l & 3;
        int row0 = (2 * mt) * H + j0 + r;        // gate 2mt, unit r
        int row1 = (2 * mt + 1) * H + j0 + r;    // gate 2mt+1, unit r
        int k0 = kc * 16 + 2 * t4;
        float2 f0 = *(const float2*)&Whh[(size_t)row0 * H + k0];
        float2 f1 = *(const float2*)&Whh[(size_t)row1 * H + k0];
        float2 f2 = *(const float2*)&Whh[(size_t)row0 * H + k0 + 8];
        float2 f3 = *(const float2*)&Whh[(size_t)row1 * H + k0 + 8];
        __half2 h0 = __float22half2_rn(f0);
        __half2 h1 = __float22half2_rn(f1);
        __half2 h2 = __float22half2_rn(f2);
        __half2 h3 = __float22half2_rn(f3);
        uint4 v;
        v.x = *(unsigned*)&h0; v.y = *(unsigned*)&h1;
        v.z = *(unsigned*)&h2; v.w = *(unsigned*)&h3;
        Wstage[s0] = v;
    }
    __syncthreads();

    const int warp = tid >> 5;
    const int lane = tid & 31;
    const int mh = warp & 1;            // m16 tile
    const int kq = warp >> 1;           // k-quarter 0..3
    const int gID = lane >> 2;
    const int t4 = lane & 3;

    // ---- W k-chunks into registers: wreg[i] = kc (4i + kq) ----
    uint4 wreg[16];
#pragma unroll
    for (int i = 0; i < 16; i++)
        wreg[i] = Wstage[(mh * 64 + 4 * i + kq) * 32 + lane];
    __syncthreads();    // Wstage region now free for Hs

    const __half* hp0 = &Hs[(0 * 8 + gID) * HS_PITCH + 2 * t4];
    const __half* hp1 = &Hs[(1 * 8 + gID) * HS_PITCH + 2 * t4];
    const __half* hp2 = &Hs[(2 * 8 + gID) * HS_PITCH + 2 * t4];
    const __half* hp3 = &Hs[(3 * 8 + gID) * HS_PITCH + 2 * t4];
    float* Gw = Gs + kq * (32 * 36);

    // item mapping: jj = unit 0..7, bb = batch 0..31
    const int jj = tid & 7;
    const int bb = tid >> 3;
    float c_reg = (d ? c0b : c0f)[bb * H + j0 + jj];

    const size_t xg_dir = (size_t)d * M_ALL * G4;

    float xi[4];
    {
        int te0 = d ? (T - 1) : 0;
        const __half* xgp = g_xg + xg_dir + (size_t)(te0 * B + bb) * G4 + j0 + jj;
        xi[0] = __half2float(__ldcg(xgp));
        xi[1] = __half2float(__ldcg(xgp + H));
        xi[2] = __half2float(__ldcg(xgp + 2 * H));
        xi[3] = __half2float(__ldcg(xgp + 3 * H));
    }

    float a0[4], a1[4], a2[4], a3[4];

// mma over i in [I0, I1): kc = 4i + kq
#define MMA_RANGE(I0, I1) do {                                             \
    _Pragma("unroll")                                                      \
    for (int i = (I0); i < (I1); i++) {                                    \
        int koff = (4 * i + kq) * 16;                                      \
        unsigned b00 = *(const unsigned*)(hp0 + koff);                     \
        unsigned b01 = *(const unsigned*)(hp0 + koff + 8);                 \
        mma_fp16(a0, wreg[i], b00, b01);                                   \
        unsigned b10 = *(const unsigned*)(hp1 + koff);                     \
        unsigned b11 = *(const unsigned*)(hp1 + koff + 8);                 \
        mma_fp16(a1, wreg[i], b10, b11);                                   \
        unsigned b20 = *(const unsigned*)(hp2 + koff);                     \
        unsigned b21 = *(const unsigned*)(hp2 + koff + 8);                 \
        mma_fp16(a2, wreg[i], b20, b21);                                   \
        unsigned b30 = *(const unsigned*)(hp3 + koff);                     \
        unsigned b31 = *(const unsigned*)(hp3 + koff + 8);                 \
        mma_fp16(a3, wreg[i], b30, b31);                                   \
    }                                                                      \
} while (0)

    for (int t = 0; t < T; t++) {
        const int p = t & 1;
        const int t_eff = d ? (T - 1 - t) : t;
        const uint4* src = (const uint4*)&g_hstage[p][d][0][0];

        // ---- stage h in two k-halves (cols 0..63, then 64..127) ----
#pragma unroll
        for (int i = 0; i < 8; i++) {
            int j = tid + i * 256;
            int b = j >> 6, q = j & 63;
            unsigned dst = (unsigned)__cvta_generic_to_shared(
                &Hs[b * HS_PITCH + q * 8]);
            CP_ASYNC16(dst, src + b * 128 + q);
        }
        CP_COMMIT();
#pragma unroll
        for (int i = 0; i < 8; i++) {
            int j = tid + i * 256;
            int b = j >> 6, q = (j & 63) + 64;
            unsigned dst = (unsigned)__cvta_generic_to_shared(
                &Hs[b * HS_PITCH + q * 8]);
            CP_ASYNC16(dst, src + b * 128 + q);
        }
        CP_COMMIT();

#pragma unroll
        for (int q = 0; q < 4; q++) { a0[q] = a1[q] = a2[q] = a3[q] = 0.f; }

        // ---- mma on half 0 (kc < 32 since 4i+kq < 32 for i < 8) ----
        CP_WAIT1();
        __syncthreads();
        MMA_RANGE(0, 8);

        CP_WAIT0();
        __syncthreads();
        MMA_RANGE(8, 16);

        // ---- stage gate pre-activations (per k-quarter buffer) ----
        {
            int row = mh * 16 + gID;
            int cb = 2 * t4;
            float* r0 = Gw + row * 36;
            float* r1 = Gw + (row + 8) * 36;
            r0[cb]      = a0[0]; r0[cb + 1]  = a0[1];
            r1[cb]      = a0[2]; r1[cb + 1]  = a0[3];
            r0[cb + 8]  = a1[0]; r0[cb + 9]  = a1[1];
            r1[cb + 8]  = a1[2]; r1[cb + 9]  = a1[3];
            r0[cb + 16] = a2[0]; r0[cb + 17] = a2[1];
            r1[cb + 16] = a2[2]; r1[cb + 17] = a2[3];
            r0[cb + 24] = a3[0]; r0[cb + 25] = a3[1];
            r1[cb + 24] = a3[2]; r1[cb + 25] = a3[3];
        }
        __syncthreads();

        // ---- pointwise cell update (one item per thread) ----
        float hn_keep;
        {
            float ig = Gs[0 * 1152 + (0  + jj) * 36 + bb] + Gs[1 * 1152 + (0  + jj) * 36 + bb]
                     + Gs[2 * 1152 + (0  + jj) * 36 + bb] + Gs[3 * 1152 + (0  + jj) * 36 + bb]
                     + xi[0];
            float fg = Gs[0 * 1152 + (8  + jj) * 36 + bb] + Gs[1 * 1152 + (8  + jj) * 36 + bb]
                     + Gs[2 * 1152 + (8  + jj) * 36 + bb] + Gs[3 * 1152 + (8  + jj) * 36 + bb]
                     + xi[1];
            float gg = Gs[0 * 1152 + (16 + jj) * 36 + bb] + Gs[1 * 1152 + (16 + jj) * 36 + bb]
                     + Gs[2 * 1152 + (16 + jj) * 36 + bb] + Gs[3 * 1152 + (16 + jj) * 36 + bb]
                     + xi[2];
            float og = Gs[0 * 1152 + (24 + jj) * 36 + bb] + Gs[1 * 1152 + (24 + jj) * 36 + bb]
                     + Gs[2 * 1152 + (24 + jj) * 36 + bb] + Gs[3 * 1152 + (24 + jj) * 36 + bb]
                     + xi[3];
            float igs = sig_(ig);
            float fgs = sig_(fg);
            float ogs = sig_(og);
            float ggt = tanh_(gg);
            float cn = fgs * c_reg + igs * ggt;
            c_reg = cn;
            hn_keep = ogs * tanh_(cn);
            g_hstage[p ^ 1][d][bb][j0 + jj] = __float2half(hn_keep);
        }

        __syncthreads();    // hstage writes done CTA-wide before release

        if (t + 1 < T && tid == 0) red_release_add(&g_bar[d]);

        // hidden behind the barrier: out store + next xg prefetch
        out[(size_t)t_eff * B * OUT_COLS + (size_t)bb * OUT_COLS
            + (size_t)d * H + j0 + jj] = hn_keep;
        if (t + 1 < T) {
            int ten = d ? (T - 2 - t) : (t + 1);
            const __half* xgp = g_xg + xg_dir + (size_t)(ten * B + bb) * G4 + j0 + jj;
            xi[0] = __half2float(__ldcg(xgp));
            xi[1] = __half2float(__ldcg(xgp + H));
            xi[2] = __half2float(__ldcg(xgp + 2 * H));
            xi[3] = __half2float(__ldcg(xgp + 3 * H));
            if (tid == 0) {
                unsigned tgt = (unsigned)CTAS_PER_DIR * (t + 1);
                while (ld_acquire(&g_bar[d]) < tgt) { }
            }
            __syncthreads();
        }
    }

    g_c[(size_t)d * B * H + (size_t)bb * H + j0 + jj] = c_reg;
}

// ---------------------------------------------------------------------------
__global__ void finalize_kernel(float* __restrict__ out) {
    int i = blockIdx.x * blockDim.x + threadIdx.x;
    if (i >= B * H) return;
    int b = i >> 10;
    int j = i & (H - 1);
    float* tail = out + OUT_MAIN;
    tail[i]             = out[(size_t)(T - 1) * B * OUT_COLS + (size_t)b * OUT_COLS + j];
    tail[B * H + i]     = g_c[i];
    tail[2 * B * H + i] = out[(size_t)b * OUT_COLS + H + j];
    tail[3 * B * H + i] = g_c[B * H + i];
}

// ---------------------------------------------------------------------------
extern "C" void kernel_launch(void* const* d_in, const int* in_sizes, int n_in,
                              void* d_out, int out_size) {
    const float* x    = (const float*)d_in[0];
    const float* h0f  = (const float*)d_in[1];
    const float* c0f  = (const float*)d_in[2];
    const float* h0b  = (const float*)d_in[3];
    const float* c0b  = (const float*)d_in[4];
    const float* Wihf = (const float*)d_in[5];
    const float* Whhf = (const float*)d_in[6];
    const float* bihf = (const float*)d_in[7];
    const float* bhhf = (const float*)d_in[8];
    const float* Wihb = (const float*)d_in[9];
    const float* Whhb = (const float*)d_in[10];
    const float* bihb = (const float*)d_in[11];
    const float* bhhb = (const float*)d_in[12];
    float* out = (float*)d_out;

    static int smem_set = 0;
    if (!smem_set) {
        cudaFuncSetAttribute(lstm_persistent,
                             cudaFuncAttributeMaxDynamicSharedMemorySize,
                             SMEM_BYTES);
        cudaFuncSetAttribute(xg_gemm_hmma,
                             cudaFuncAttributeMaxDynamicSharedMemorySize,
                             GEMM_SMEM);
        smem_set = 1;
    }

    init_kernel<<<(B * H + 255) / 256, 256>>>(h0f, h0b);
    prepack_x<<<(M16 * KC * 32 + 255) / 256, 256>>>(x);
    prepack_w<<<(N16 * KC * 32 + 255) / 256, 256>>>(Wihf, Wihb);

    dim3 grid_xg(N_ALL / 64, M_ALL / 256);   // (128, 64)
    xg_gemm_hmma<<<grid_xg, 128, GEMM_SMEM>>>(bihf, bhhf, bihb, bhhb);

    lstm_persistent<<<CTAS, THREADS, SMEM_BYTES>>>(Whhf, Whhb, c0f, c0b, out);

    finalize_kernel<<<(B * H + 255) / 256, 256>>>(out);
}

// round 16
// speedup vs baseline: 1.0541x; 1.0541x over previous
#include <cuda_runtime.h>
#include <cuda_fp16.h>
#include <math.h>

// ---------------------------------------------------------------------------
// Bidirectional LSTM: T=512, B=32, I=1024, H=1024.
// Round 16: exact R10 (best: 3060us) + zero-risk micro-reductions:
//   - pointwise tail vectorized: unit-pair mapping -> half2/float2 stores,
//     half2 xg prefetch, single rep (was 2).
//   - init fused into prepack_x (one fewer launch).
// GEMM, staging, mma loop, barrier: byte-identical to R10.
// ---------------------------------------------------------------------------

namespace {
constexpr int T = 512;
constexpr int B = 32;
constexpr int I = 1024;
constexpr int H = 1024;
constexpr int G4 = 4 * H;          // 4096
constexpr int N_ALL = 2 * G4;      // 8192
constexpr int OUT_COLS = 2 * H;    // 2048
constexpr int M_ALL = T * B;       // 16384
constexpr long long OUT_MAIN = (long long)T * B * OUT_COLS;

constexpr int CTAS = 128;          // 2 dirs x 64 slices of 16 units
constexpr int THREADS = 256;
constexpr int CTAS_PER_DIR = 64;

constexpr int HS_PITCH = 1032;
constexpr int SMEM_W  = 4 * 64 * 32 * 16;           // 131072 (prologue only)
constexpr int SMEM_HS = 32 * HS_PITCH * 2;          // 66048
constexpr int SMEM_G0 = SMEM_W + SMEM_HS;
constexpr int SMEM_G1 = SMEM_G0 + 64 * 33 * 4;
constexpr int SMEM_BYTES = SMEM_G1 + 64 * 33 * 4;   // 214016

constexpr int KC = 64;
constexpr int M16 = M_ALL / 16;    // 1024
constexpr int N16 = N_ALL / 16;    // 512

// GEMM: 3 stages x (A 1024 + B 256) uint4
constexpr int GEMM_SMEM = 3 * (1024 + 256) * 16;    // 61440
}

__device__ __half g_xg[2LL * M_ALL * G4];
__device__ float g_c[2 * B * H];
__device__ __half g_hstage[2][2][B][H];
__device__ unsigned g_bar[2];
__device__ uint4 g_xa[(long long)M16 * KC * 32];
__device__ uint4 g_wb[(long long)N16 * KC * 32];

__device__ __forceinline__ void mma_fp16(float* d, const uint4& a,
                                         unsigned b0, unsigned b1) {
    asm volatile(
        "mma.sync.aligned.m16n8k16.row.col.f32.f16.f16.f32 "
        "{%0,%1,%2,%3}, {%4,%5,%6,%7}, {%8,%9}, {%0,%1,%2,%3};"
        : "+f"(d[0]), "+f"(d[1]), "+f"(d[2]), "+f"(d[3])
        : "r"(a.x), "r"(a.y), "r"(a.z), "r"(a.w), "r"(b0), "r"(b1));
}

__device__ __forceinline__ float sig_(float x) {
    return 1.f / (1.f + __expf(-x));
}
__device__ __forceinline__ float tanh_(float x) {
    float t = __expf(-2.f * fabsf(x));
    float r = (1.f - t) / (1.f + t);
    return x < 0.f ? -r : r;
}

__device__ __forceinline__ void red_release_add(unsigned* p) {
    asm volatile("red.release.gpu.global.add.u32 [%0], %1;"
                 :: "l"(p), "r"(1u) : "memory");
}
__device__ __forceinline__ unsigned ld_acquire(const unsigned* p) {
    unsigned v;
    asm volatile("ld.acquire.gpu.global.u32 %0, [%1];"
                 : "=r"(v) : "l"(p) : "memory");
    return v;
}

#define CP_ASYNC16(smem_u32, gptr) \
    asm volatile("cp.async.cg.shared.global [%0], [%1], 16;" \
                 :: "r"(smem_u32), "l"(gptr))
#define CP_COMMIT() asm volatile("cp.async.commit_group;")
#define CP_WAIT1() asm volatile("cp.async.wait_group 1;")
#define CP_WAIT0() asm volatile("cp.async.wait_group 0;")

// ---------------------------------------------------------------------------
// prepack_x + init fused (x fragments, hstage init, barrier reset)
// ---------------------------------------------------------------------------
__global__ void prepack_x(const float* __restrict__ x,
                          const float* __restrict__ h0f,
                          const float* __restrict__ h0b) {
    int idx = blockIdx.x * blockDim.x + threadIdx.x;
    if (idx == 0) { g_bar[0] = 0; g_bar[1] = 0; }
    if (idx < B * H) {
        int b = idx >> 10;
        int k = idx & 1023;
        g_hstage[0][0][b][k] = __float2half(h0f[idx]);
        g_hstage[0][1][b][k] = __float2half(h0b[idx]);
    }
    if (idx >= M16 * KC * 32) return;
    int lane = idx & 31;
    int kc = (idx >> 5) & 63;
    int m16 = idx >> 11;
    int r = lane >> 2;
    int t4 = lane & 3;
    int m0 = m16 * 16;
    int k0 = kc * 16 + 2 * t4;
    float2 f0 = *(const float2*)&x[(size_t)(m0 + r) * I + k0];
    float2 f1 = *(const float2*)&x[(size_t)(m0 + r + 8) * I + k0];
    float2 f2 = *(const float2*)&x[(size_t)(m0 + r) * I + k0 + 8];
    float2 f3 = *(const float2*)&x[(size_t)(m0 + r + 8) * I + k0 + 8];
    __half2 h0 = __float22half2_rn(f0);
    __half2 h1 = __float22half2_rn(f1);
    __half2 h2 = __float22half2_rn(f2);
    __half2 h3 = __float22half2_rn(f3);
    uint4 v;
    v.x = *(unsigned*)&h0; v.y = *(unsigned*)&h1;
    v.z = *(unsigned*)&h2; v.w = *(unsigned*)&h3;
    g_xa[idx] = v;
}

__global__ void prepack_w(const float* __restrict__ Wf,
                          const float* __restrict__ Wb) {
    int idx = blockIdx.x * blockDim.x + threadIdx.x;
    if (idx >= N16 * KC * 32) return;
    int lane = idx & 31;
    int kc = (idx >> 5) & 63;
    int n16 = idx >> 11;
    int n = n16 * 16;
    const float* W = (n >= G4) ? Wb : Wf;
    int g = n & (G4 - 1);
    int r = lane >> 2;
    int t4 = lane & 3;
    int k0 = kc * 16 + 2 * t4;
    float2 f0 = *(const float2*)&W[(size_t)(g + r) * H + k0];
    float2 f1 = *(const float2*)&W[(size_t)(g + r) * H + k0 + 8];
    float2 f2 = *(const float2*)&W[(size_t)(g + r + 8) * H + k0];
    float2 f3 = *(const float2*)&W[(size_t)(g + r + 8) * H + k0 + 8];
    __half2 h0 = __float22half2_rn(f0);
    __half2 h1 = __float22half2_rn(f1);
    __half2 h2 = __float22half2_rn(f2);
    __half2 h3 = __float22half2_rn(f3);
    uint4 v;
    v.x = *(unsigned*)&h0; v.y = *(unsigned*)&h1;
    v.z = *(unsigned*)&h2; v.w = *(unsigned*)&h3;
    g_wb[idx] = v;
}

// ---------------------------------------------------------------------------
// xg GEMM (exact R10): CTA tile 256x64, 128 threads, 4 warps m128n32,
// BK=32, 3-stage cp.async, 2 CTAs/SM. grid = (128, 64).
// ---------------------------------------------------------------------------
__global__ __launch_bounds__(128, 2)
void xg_gemm_hmma(const float* __restrict__ bihf, const float* __restrict__ bhhf,
                  const float* __restrict__ bihb, const float* __restrict__ bhhb) {
    extern __shared__ char gsm[];
    uint4* sA = (uint4*)gsm;                    // 3 x 1024
    uint4* sB = (uint4*)(gsm + 3 * 16384);      // 3 x 256

    const int tid = threadIdx.x;
    const int m0 = blockIdx.y * 256;
    const int n0 = blockIdx.x * 64;
    const int m16g0 = m0 >> 4;
    const int n16g0 = n0 >> 4;

    const int warp = tid >> 5;
    const int lane = tid & 31;
    const int wm = warp >> 1;
    const int wn = warp & 1;
    const int gID = lane >> 2;
    const int t4 = lane & 3;

    float acc[8][4][4];
#pragma unroll
    for (int i = 0; i < 8; i++)
#pragma unroll
        for (int j = 0; j < 4; j++)
#pragma unroll
            for (int q = 0; q < 4; q++) acc[i][j][q] = 0.f;

    int a_16l[8], a_kcl[8], a_lane[8];
#pragma unroll
    for (int j = 0; j < 8; j++) {
        int i = tid + j * 128;
        a_16l[j] = i >> 6;
        a_kcl[j] = (i >> 5) & 1;
        a_lane[j] = i & 31;
    }
    int b_16l[2], b_kcl[2], b_lane[2];
#pragma unroll
    for (int j = 0; j < 2; j++) {
        int i = tid + j * 128;
        b_16l[j] = i >> 6;
        b_kcl[j] = (i >> 5) & 1;
        b_lane[j] = i & 31;
    }

    auto issue_stage = [&](int buf, int ks) {
#pragma unroll
        for (int j = 0; j < 8; j++) {
            const uint4* src = g_xa +
                ((size_t)(m16g0 + a_16l[j]) * KC + ks * 2 + a_kcl[j]) * 32 + a_lane[j];
            unsigned dst = (unsigned)__cvta_generic_to_shared(
                &sA[buf * 1024 + (a_16l[j] * 2 + a_kcl[j]) * 32 + a_lane[j]]);
            CP_ASYNC16(dst, src);
        }
#pragma unroll
        for (int j = 0; j < 2; j++) {
            const uint4* src = g_wb +
                ((size_t)(n16g0 + b_16l[j]) * KC + ks * 2 + b_kcl[j]) * 32 + b_lane[j];
            unsigned dst = (unsigned)__cvta_generic_to_shared(
                &sB[buf * 256 + (b_16l[j] * 2 + b_kcl[j]) * 32 + b_lane[j]]);
            CP_ASYNC16(dst, src);
        }
        CP_COMMIT();
    };

    issue_stage(0, 0);
    issue_stage(1, 1);

    int cur = 0;
    for (int ks = 0; ks < 32; ks++) {
        if (ks < 31) { CP_WAIT1(); } else { CP_WAIT0(); }
        __syncthreads();
        if (ks + 2 < 32) {
            int nbuf = cur + 2;
            if (nbuf >= 3) nbuf -= 3;
            issue_stage(nbuf, ks + 2);
        }

#pragma unroll
        for (int kcl = 0; kcl < 2; kcl++) {
            uint4 b[2];
#pragma unroll
            for (int j = 0; j < 2; j++)
                b[j] = sB[cur * 256 + ((wn * 2 + j) * 2 + kcl) * 32 + lane];
#pragma unroll
            for (int i = 0; i < 8; i++) {
                uint4 a = sA[cur * 1024 + ((wm * 8 + i) * 2 + kcl) * 32 + lane];
#pragma unroll
                for (int j = 0; j < 2; j++) {
                    mma_fp16(acc[i][2 * j],     a, b[j].x, b[j].y);
                    mma_fp16(acc[i][2 * j + 1], a, b[j].z, b[j].w);
                }
            }
        }
        cur++;
        if (cur == 3) cur = 0;
    }

    const int d = n0 >> 12;
    const float* bih = d ? bihb : bihf;
    const float* bhh = d ? bhhb : bhhf;
    __half* outd = g_xg + (size_t)d * M_ALL * G4;

#pragma unroll
    for (int jj = 0; jj < 4; jj++) {
        int col = n0 + wn * 32 + jj * 8 + 2 * t4;
        int g = col & (G4 - 1);
        float bx = bih[g] + bhh[g];
        float by = bih[g + 1] + bhh[g + 1];
#pragma unroll
        for (int i = 0; i < 8; i++) {
            int row0 = m0 + wm * 128 + i * 16 + gID;
            __half2 v0 = __floats2half2_rn(acc[i][jj][0] + bx, acc[i][jj][1] + by);
            __half2 v1 = __floats2half2_rn(acc[i][jj][2] + bx, acc[i][jj][3] + by);
            *(__half2*)&outd[(size_t)row0 * G4 + g] = v0;
            *(__half2*)&outd[(size_t)(row0 + 8) * G4 + g] = v1;
        }
    }
}

// ---------------------------------------------------------------------------
// Persistent recurrence kernel (R10 + vectorized pointwise tail).
// Warp = (mw = gate, kh = k-parity); warp kh owns kc = 2i + kh, i=0..31.
// Pointwise: thread -> (unit pair jj2, batch bb), one rep.
// ---------------------------------------------------------------------------
__global__ __launch_bounds__(THREADS, 1)
void lstm_persistent(const float* __restrict__ Whhf,
                     const float* __restrict__ Whhb,
                     const float* __restrict__ c0f,
                     const float* __restrict__ c0b,
                     float* __restrict__ out) {
    extern __shared__ char smem[];
    uint4*  Wf = (uint4*)smem;                       // prologue staging only
    __half* Hs = (__half*)(smem + SMEM_W);
    float*  Gs0 = (float*)(smem + SMEM_G0);
    float*  Gs1 = (float*)(smem + SMEM_G1);

    const int tid = threadIdx.x;
    const int d = blockIdx.x >> 6;
    const int s = blockIdx.x & 63;
    const int j0 = s * 16;
    const float* Whh = d ? Whhb : Whhf;

    // ---- prepack W slice into fp16 fragment layout (smem, prologue) ----
    for (int s0 = tid; s0 < 4 * 64 * 32; s0 += THREADS) {
        int l  = s0 & 31;
        int kc = (s0 >> 5) & 63;
        int mw = s0 >> 11;
        int r  = l >> 2;
        int t4 = l & 3;
        int row0 = mw * H + j0 + r;
        int row1 = row0 + 8;
        int k0 = kc * 16 + 2 * t4;
        float2 f0 = *(const float2*)&Whh[(size_t)row0 * H + k0];
        float2 f1 = *(const float2*)&Whh[(size_t)row1 * H + k0];
        float2 f2 = *(const float2*)&Whh[(size_t)row0 * H + k0 + 8];
        float2 f3 = *(const float2*)&Whh[(size_t)row1 * H + k0 + 8];
        __half2 h0 = __float22half2_rn(f0);
        __half2 h1 = __float22half2_rn(f1);
        __half2 h2 = __float22half2_rn(f2);
        __half2 h3 = __float22half2_rn(f3);
        uint4 v;
        v.x = *(unsigned*)&h0; v.y = *(unsigned*)&h1;
        v.z = *(unsigned*)&h2; v.w = *(unsigned*)&h3;
        Wf[s0] = v;
    }
    __syncthreads();

    const int warp = tid >> 5;
    const int lane = tid & 31;
    const int mw = warp & 3;            // gate / m16 tile
    const int kh = warp >> 2;           // k-parity 0/1
    const int gID = lane >> 2;
    const int t4 = lane & 3;

    // ---- W k-chunks into registers: wreg[i] = kc (2i + kh) ----
    const uint4* wfrag = Wf + mw * 2048 + kh * 32 + lane;
    uint4 wreg[32];
#pragma unroll
    for (int i = 0; i < 32; i++) wreg[i] = wfrag[i * 64];

    const __half* hp0 = &Hs[(0 * 8 + gID) * HS_PITCH + 2 * t4];
    const __half* hp1 = &Hs[(1 * 8 + gID) * HS_PITCH + 2 * t4];
    const __half* hp2 = &Hs[(2 * 8 + gID) * HS_PITCH + 2 * t4];
    const __half* hp3 = &Hs[(3 * 8 + gID) * HS_PITCH + 2 * t4];
    float* Gw = kh ? Gs1 : Gs0;

    // ---- pointwise mapping: unit pair jj2 = 2*(tid&7), batch bb = tid>>3 ----
    const int jj2 = (tid & 7) * 2;
    const int bb = tid >> 3;
    float2 c_reg;
    {
        const float* c0 = d ? c0b : c0f;
        c_reg.x = c0[bb * H + j0 + jj2];
        c_reg.y = c0[bb * H + j0 + jj2 + 1];
    }

    const size_t xg_dir = (size_t)d * M_ALL * G4;

    float2 xig[4];   // per gate, (unit jj2, unit jj2+1)
    {
        int te0 = d ? (T - 1) : 0;
        const __half* xgp = g_xg + xg_dir + (size_t)(te0 * B + bb) * G4 + j0 + jj2;
        xig[0] = __half22float2(__ldcg((const __half2*)(xgp)));
        xig[1] = __half22float2(__ldcg((const __half2*)(xgp + H)));
        xig[2] = __half22float2(__ldcg((const __half2*)(xgp + 2 * H)));
        xig[3] = __half22float2(__ldcg((const __half2*)(xgp + 3 * H)));
    }

    float a0[4], a1[4], a2[4], a3[4];

// mma over i in [I0, I1): kc = 2i + kh
#define MMA_RANGE(I0, I1) do {                                             \
    _Pragma("unroll")                                                      \
    for (int i = (I0); i < (I1); i++) {                                    \
        int koff = (2 * i + kh) * 16;                                      \
        unsigned b00 = *(const unsigned*)(hp0 + koff);                     \
        unsigned b01 = *(const unsigned*)(hp0 + koff + 8);                 \
        mma_fp16(a0, wreg[i], b00, b01);                                   \
        unsigned b10 = *(const unsigned*)(hp1 + koff);                     \
        unsigned b11 = *(const unsigned*)(hp1 + koff + 8);                 \
        mma_fp16(a1, wreg[i], b10, b11);                                   \
        unsigned b20 = *(const unsigned*)(hp2 + koff);                     \
        unsigned b21 = *(const unsigned*)(hp2 + koff + 8);                 \
        mma_fp16(a2, wreg[i], b20, b21);                                   \
        unsigned b30 = *(const unsigned*)(hp3 + koff);                     \
        unsigned b31 = *(const unsigned*)(hp3 + koff + 8);                 \
        mma_fp16(a3, wreg[i], b30, b31);                                   \
    }                                                                      \
} while (0)

    for (int t = 0; t < T; t++) {
        const int p = t & 1;
        const int t_eff = d ? (T - 1 - t) : t;
        const uint4* src = (const uint4*)&g_hstage[p][d][0][0];

        // ---- stage h in two k-halves (cols 0..63, then 64..127) ----
#pragma unroll
        for (int i = 0; i < 8; i++) {
            int j = tid + i * 256;
            int b = j >> 6, q = j & 63;
            unsigned dst = (unsigned)__cvta_generic_to_shared(
                &Hs[b * HS_PITCH + q * 8]);
            CP_ASYNC16(dst, src + b * 128 + q);
        }
        CP_COMMIT();
#pragma unroll
        for (int i = 0; i < 8; i++) {
            int j = tid + i * 256;
            int b = j >> 6, q = (j & 63) + 64;
            unsigned dst = (unsigned)__cvta_generic_to_shared(
                &Hs[b * HS_PITCH + q * 8]);
            CP_ASYNC16(dst, src + b * 128 + q);
        }
        CP_COMMIT();

#pragma unroll
        for (int q = 0; q < 4; q++) { a0[q] = a1[q] = a2[q] = a3[q] = 0.f; }

        // ---- mma on half 0 while half 1's latency drains ----
        CP_WAIT1();
        __syncthreads();
        MMA_RANGE(0, 16);

        CP_WAIT0();
        __syncthreads();
        MMA_RANGE(16, 32);

        // ---- stage gate pre-activations (per k-parity buffer) ----
        {
            int row = mw * 16 + gID;
            int cb = 2 * t4;
            float* r0 = Gw + row * 33;
            float* r1 = Gw + (row + 8) * 33;
            r0[cb]      = a0[0]; r0[cb + 1]  = a0[1];
            r1[cb]      = a0[2]; r1[cb + 1]  = a0[3];
            r0[cb + 8]  = a1[0]; r0[cb + 9]  = a1[1];
            r1[cb + 8]  = a1[2]; r1[cb + 9]  = a1[3];
            r0[cb + 16] = a2[0]; r0[cb + 17] = a2[1];
            r1[cb + 16] = a2[2]; r1[cb + 17] = a2[3];
            r0[cb + 24] = a3[0]; r0[cb + 25] = a3[1];
            r1[cb + 24] = a3[2]; r1[cb + 25] = a3[3];
        }
        __syncthreads();

        // ---- pointwise cell update (unit pair per thread, one rep) ----
        float hn0, hn1;
        {
            int jA = jj2, jB = jj2 + 1;
            float igA = Gs0[(0  + jA) * 33 + bb] + Gs1[(0  + jA) * 33 + bb] + xig[0].x;
            float igB = Gs0[(0  + jB) * 33 + bb] + Gs1[(0  + jB) * 33 + bb] + xig[0].y;
            float fgA = Gs0[(16 + jA) * 33 + bb] + Gs1[(16 + jA) * 33 + bb] + xig[1].x;
            float fgB = Gs0[(16 + jB) * 33 + bb] + Gs1[(16 + jB) * 33 + bb] + xig[1].y;
            float ggA = Gs0[(32 + jA) * 33 + bb] + Gs1[(32 + jA) * 33 + bb] + xig[2].x;
            float ggB = Gs0[(32 + jB) * 33 + bb] + Gs1[(32 + jB) * 33 + bb] + xig[2].y;
            float ogA = Gs0[(48 + jA) * 33 + bb] + Gs1[(48 + jA) * 33 + bb] + xig[3].x;
            float ogB = Gs0[(48 + jB) * 33 + bb] + Gs1[(48 + jB) * 33 + bb] + xig[3].y;
            igA = sig_(igA); igB = sig_(igB);
            fgA = sig_(fgA); fgB = sig_(fgB);
            ogA = sig_(ogA); ogB = sig_(ogB);
            ggA = tanh_(ggA); ggB = tanh_(ggB);
            float cnA = fgA * c_reg.x + igA * ggA;
            float cnB = fgB * c_reg.y + igB * ggB;
            c_reg.x = cnA;
            c_reg.y = cnB;
            hn0 = ogA * tanh_(cnA);
            hn1 = ogB * tanh_(cnB);
            *(__half2*)&g_hstage[p ^ 1][d][bb][j0 + jj2] =
                __floats2half2_rn(hn0, hn1);
        }

        __syncthreads();    // hstage writes done CTA-wide before release

        if (t + 1 < T && tid == 0) red_release_add(&g_bar[d]);

        // hidden behind the barrier: out store + next xg prefetch
        *(float2*)&out[(size_t)t_eff * B * OUT_COLS + (size_t)bb * OUT_COLS
                       + (size_t)d * H + j0 + jj2] = make_float2(hn0, hn1);
        if (t + 1 < T) {
            int ten = d ? (T - 2 - t) : (t + 1);
            const __half* xgp = g_xg + xg_dir
                              + (size_t)(ten * B + bb) * G4 + j0 + jj2;
            xig[0] = __half22float2(__ldcg((const __half2*)(xgp)));
            xig[1] = __half22float2(__ldcg((const __half2*)(xgp + H)));
            xig[2] = __half22float2(__ldcg((const __half2*)(xgp + 2 * H)));
            xig[3] = __half22float2(__ldcg((const __half2*)(xgp + 3 * H)));
            if (tid == 0) {
                unsigned tgt = (unsigned)CTAS_PER_DIR * (t + 1);
                while (ld_acquire(&g_bar[d]) < tgt) { }
            }
            __syncthreads();
        }
    }

    *(float2*)&g_c[(size_t)d * B * H + (size_t)bb * H + j0 + jj2] = c_reg;
}

// ---------------------------------------------------------------------------
__global__ void finalize_kernel(float* __restrict__ out) {
    int i = blockIdx.x * blockDim.x + threadIdx.x;
    if (i >= B * H) return;
    int b = i >> 10;
    int j = i & (H - 1);
    float* tail = out + OUT_MAIN;
    tail[i]             = out[(size_t)(T - 1) * B * OUT_COLS + (size_t)b * OUT_COLS + j];
    tail[B * H + i]     = g_c[i];
    tail[2 * B * H + i] = out[(size_t)b * OUT_COLS + H + j];
    tail[3 * B * H + i] = g_c[B * H + i];
}

// ---------------------------------------------------------------------------
extern "C" void kernel_launch(void* const* d_in, const int* in_sizes, int n_in,
                              void* d_out, int out_size) {
    const float* x    = (const float*)d_in[0];
    const float* h0f  = (const float*)d_in[1];
    const float* c0f  = (const float*)d_in[2];
    const float* h0b  = (const float*)d_in[3];
    const float* c0b  = (const float*)d_in[4];
    const float* Wihf = (const float*)d_in[5];
    const float* Whhf = (const float*)d_in[6];
    const float* bihf = (const float*)d_in[7];
    const float* bhhf = (const float*)d_in[8];
    const float* Wihb = (const float*)d_in[9];
    const float* Whhb = (const float*)d_in[10];
    const float* bihb = (const float*)d_in[11];
    const float* bhhb = (const float*)d_in[12];
    float* out = (float*)d_out;

    static int smem_set = 0;
    if (!smem_set) {
        cudaFuncSetAttribute(lstm_persistent,
                             cudaFuncAttributeMaxDynamicSharedMemorySize,
                             SMEM_BYTES);
        cudaFuncSetAttribute(xg_gemm_hmma,
                             cudaFuncAttributeMaxDynamicSharedMemorySize,
                             GEMM_SMEM);
        smem_set = 1;
    }

    prepack_x<<<(M16 * KC * 32 + 255) / 256, 256>>>(x, h0f, h0b);
    prepack_w<<<(N16 * KC * 32 + 255) / 256, 256>>>(Wihf, Wihb);

    dim3 grid_xg(N_ALL / 64, M_ALL / 256);   // (128, 64)
    xg_gemm_hmma<<<grid_xg, 128, GEMM_SMEM>>>(bihf, bhhf, bihb, bhhb);

    lstm_persistent<<<CTAS, THREADS, SMEM_BYTES>>>(Whhf, Whhb, c0f, c0b, out);

    finalize_kernel<<<(B * H + 255) / 256, 256>>>(out);
}

// round 17
// speedup vs baseline: 1.0807x; 1.0252x over previous
#include <cuda_runtime.h>
#include <cuda_fp16.h>
#include <math.h>

// ---------------------------------------------------------------------------
// Bidirectional LSTM: T=512, B=32, I=1024, H=1024.
// Round 17: R10 byte-exact hot paths (best measured: 3059.7us).
//   - xg GEMM: m128n32 warp tile, CTA 256x64, 3-stage cp.async, 2 CTAs/SM.
//   - recurrence: 128 persistent CTAs, W fragments in registers (kc=2i+kh),
//     half-split cp.async h staging overlapped with mma, single per-dir
//     red.release counter barrier with tid0 spin; out-store + xg prefetch
//     hidden behind the barrier.
//   - only change vs R10: init fused into prepack_x (one fewer launch).
// ---------------------------------------------------------------------------

namespace {
constexpr int T = 512;
constexpr int B = 32;
constexpr int I = 1024;
constexpr int H = 1024;
constexpr int G4 = 4 * H;          // 4096
constexpr int N_ALL = 2 * G4;      // 8192
constexpr int OUT_COLS = 2 * H;    // 2048
constexpr int M_ALL = T * B;       // 16384
constexpr long long OUT_MAIN = (long long)T * B * OUT_COLS;

constexpr int CTAS = 128;          // 2 dirs x 64 slices of 16 units
constexpr int THREADS = 256;
constexpr int CTAS_PER_DIR = 64;

constexpr int HS_PITCH = 1032;
constexpr int SMEM_W  = 4 * 64 * 32 * 16;           // 131072 (prologue only)
constexpr int SMEM_HS = 32 * HS_PITCH * 2;          // 66048
constexpr int SMEM_G0 = SMEM_W + SMEM_HS;
constexpr int SMEM_G1 = SMEM_G0 + 64 * 33 * 4;
constexpr int SMEM_BYTES = SMEM_G1 + 64 * 33 * 4;   // 214016

constexpr int KC = 64;
constexpr int M16 = M_ALL / 16;    // 1024
constexpr int N16 = N_ALL / 16;    // 512

// GEMM: 3 stages x (A 1024 + B 256) uint4
constexpr int GEMM_SMEM = 3 * (1024 + 256) * 16;    // 61440
}

__device__ __half g_xg[2LL * M_ALL * G4];
__device__ float g_c[2 * B * H];
__device__ __half g_hstage[2][2][B][H];
__device__ unsigned g_bar[2];
__device__ uint4 g_xa[(long long)M16 * KC * 32];
__device__ uint4 g_wb[(long long)N16 * KC * 32];

__device__ __forceinline__ void mma_fp16(float* d, const uint4& a,
                                         unsigned b0, unsigned b1) {
    asm volatile(
        "mma.sync.aligned.m16n8k16.row.col.f32.f16.f16.f32 "
        "{%0,%1,%2,%3}, {%4,%5,%6,%7}, {%8,%9}, {%0,%1,%2,%3};"
        : "+f"(d[0]), "+f"(d[1]), "+f"(d[2]), "+f"(d[3])
        : "r"(a.x), "r"(a.y), "r"(a.z), "r"(a.w), "r"(b0), "r"(b1));
}

__device__ __forceinline__ float sig_(float x) {
    return 1.f / (1.f + __expf(-x));
}
__device__ __forceinline__ float tanh_(float x) {
    float t = __expf(-2.f * fabsf(x));
    float r = (1.f - t) / (1.f + t);
    return x < 0.f ? -r : r;
}

__device__ __forceinline__ void red_release_add(unsigned* p) {
    asm volatile("red.release.gpu.global.add.u32 [%0], %1;"
                 :: "l"(p), "r"(1u) : "memory");
}
__device__ __forceinline__ unsigned ld_acquire(const unsigned* p) {
    unsigned v;
    asm volatile("ld.acquire.gpu.global.u32 %0, [%1];"
                 : "=r"(v) : "l"(p) : "memory");
    return v;
}

#define CP_ASYNC16(smem_u32, gptr) \
    asm volatile("cp.async.cg.shared.global [%0], [%1], 16;" \
                 :: "r"(smem_u32), "l"(gptr))
#define CP_COMMIT() asm volatile("cp.async.commit_group;")
#define CP_WAIT1() asm volatile("cp.async.wait_group 1;")
#define CP_WAIT0() asm volatile("cp.async.wait_group 0;")

// ---------------------------------------------------------------------------
// prepack_x + init fused (x fragments, hstage init, barrier reset)
// ---------------------------------------------------------------------------
__global__ void prepack_x(const float* __restrict__ x,
                          const float* __restrict__ h0f,
                          const float* __restrict__ h0b) {
    int idx = blockIdx.x * blockDim.x + threadIdx.x;
    if (idx == 0) { g_bar[0] = 0; g_bar[1] = 0; }
    if (idx < B * H) {
        int b = idx >> 10;
        int k = idx & 1023;
        g_hstage[0][0][b][k] = __float2half(h0f[idx]);
        g_hstage[0][1][b][k] = __float2half(h0b[idx]);
    }
    if (idx >= M16 * KC * 32) return;
    int lane = idx & 31;
    int kc = (idx >> 5) & 63;
    int m16 = idx >> 11;
    int r = lane >> 2;
    int t4 = lane & 3;
    int m0 = m16 * 16;
    int k0 = kc * 16 + 2 * t4;
    float2 f0 = *(const float2*)&x[(size_t)(m0 + r) * I + k0];
    float2 f1 = *(const float2*)&x[(size_t)(m0 + r + 8) * I + k0];
    float2 f2 = *(const float2*)&x[(size_t)(m0 + r) * I + k0 + 8];
    float2 f3 = *(const float2*)&x[(size_t)(m0 + r + 8) * I + k0 + 8];
    __half2 h0 = __float22half2_rn(f0);
    __half2 h1 = __float22half2_rn(f1);
    __half2 h2 = __float22half2_rn(f2);
    __half2 h3 = __float22half2_rn(f3);
    uint4 v;
    v.x = *(unsigned*)&h0; v.y = *(unsigned*)&h1;
    v.z = *(unsigned*)&h2; v.w = *(unsigned*)&h3;
    g_xa[idx] = v;
}

__global__ void prepack_w(const float* __restrict__ Wf,
                          const float* __restrict__ Wb) {
    int idx = blockIdx.x * blockDim.x + threadIdx.x;
    if (idx >= N16 * KC * 32) return;
    int lane = idx & 31;
    int kc = (idx >> 5) & 63;
    int n16 = idx >> 11;
    int n = n16 * 16;
    const float* W = (n >= G4) ? Wb : Wf;
    int g = n & (G4 - 1);
    int r = lane >> 2;
    int t4 = lane & 3;
    int k0 = kc * 16 + 2 * t4;
    float2 f0 = *(const float2*)&W[(size_t)(g + r) * H + k0];
    float2 f1 = *(const float2*)&W[(size_t)(g + r) * H + k0 + 8];
    float2 f2 = *(const float2*)&W[(size_t)(g + r + 8) * H + k0];
    float2 f3 = *(const float2*)&W[(size_t)(g + r + 8) * H + k0 + 8];
    __half2 h0 = __float22half2_rn(f0);
    __half2 h1 = __float22half2_rn(f1);
    __half2 h2 = __float22half2_rn(f2);
    __half2 h3 = __float22half2_rn(f3);
    uint4 v;
    v.x = *(unsigned*)&h0; v.y = *(unsigned*)&h1;
    v.z = *(unsigned*)&h2; v.w = *(unsigned*)&h3;
    g_wb[idx] = v;
}

// ---------------------------------------------------------------------------
// xg GEMM (exact R10): CTA tile 256x64, 128 threads, 4 warps m128n32,
// BK=32, 3-stage cp.async, 2 CTAs/SM. grid = (N_ALL/64, M_ALL/256) = (128, 64).
// ---------------------------------------------------------------------------
__global__ __launch_bounds__(128, 2)
void xg_gemm_hmma(const float* __restrict__ bihf, const float* __restrict__ bhhf,
                  const float* __restrict__ bihb, const float* __restrict__ bhhb) {
    extern __shared__ char gsm[];
    uint4* sA = (uint4*)gsm;                    // 3 x 1024
    uint4* sB = (uint4*)(gsm + 3 * 16384);      // 3 x 256

    const int tid = threadIdx.x;
    const int m0 = blockIdx.y * 256;
    const int n0 = blockIdx.x * 64;
    const int m16g0 = m0 >> 4;
    const int n16g0 = n0 >> 4;

    const int warp = tid >> 5;
    const int lane = tid & 31;
    const int wm = warp >> 1;       // 0..1
    const int wn = warp & 1;        // 0..1
    const int gID = lane >> 2;
    const int t4 = lane & 3;

    float acc[8][4][4];
#pragma unroll
    for (int i = 0; i < 8; i++)
#pragma unroll
        for (int j = 0; j < 4; j++)
#pragma unroll
            for (int q = 0; q < 4; q++) acc[i][j][q] = 0.f;

    int a_16l[8], a_kcl[8], a_lane[8];
#pragma unroll
    for (int j = 0; j < 8; j++) {
        int i = tid + j * 128;
        a_16l[j] = i >> 6;
        a_kcl[j] = (i >> 5) & 1;
        a_lane[j] = i & 31;
    }
    int b_16l[2], b_kcl[2], b_lane[2];
#pragma unroll
    for (int j = 0; j < 2; j++) {
        int i = tid + j * 128;
        b_16l[j] = i >> 6;
        b_kcl[j] = (i >> 5) & 1;
        b_lane[j] = i & 31;
    }

    auto issue_stage = [&](int buf, int ks) {
#pragma unroll
        for (int j = 0; j < 8; j++) {
            const uint4* src = g_xa +
                ((size_t)(m16g0 + a_16l[j]) * KC + ks * 2 + a_kcl[j]) * 32 + a_lane[j];
            unsigned dst = (unsigned)__cvta_generic_to_shared(
                &sA[buf * 1024 + (a_16l[j] * 2 + a_kcl[j]) * 32 + a_lane[j]]);
            CP_ASYNC16(dst, src);
        }
#pragma unroll
        for (int j = 0; j < 2; j++) {
            const uint4* src = g_wb +
                ((size_t)(n16g0 + b_16l[j]) * KC + ks * 2 + b_kcl[j]) * 32 + b_lane[j];
            unsigned dst = (unsigned)__cvta_generic_to_shared(
                &sB[buf * 256 + (b_16l[j] * 2 + b_kcl[j]) * 32 + b_lane[j]]);
            CP_ASYNC16(dst, src);
        }
        CP_COMMIT();
    };

    issue_stage(0, 0);
    issue_stage(1, 1);

    int cur = 0;
    for (int ks = 0; ks < 32; ks++) {
        if (ks < 31) { CP_WAIT1(); } else { CP_WAIT0(); }
        __syncthreads();
        if (ks + 2 < 32) {
            int nbuf = cur + 2;
            if (nbuf >= 3) nbuf -= 3;
            issue_stage(nbuf, ks + 2);
        }

#pragma unroll
        for (int kcl = 0; kcl < 2; kcl++) {
            uint4 b[2];
#pragma unroll
            for (int j = 0; j < 2; j++)
                b[j] = sB[cur * 256 + ((wn * 2 + j) * 2 + kcl) * 32 + lane];
#pragma unroll
            for (int i = 0; i < 8; i++) {
                uint4 a = sA[cur * 1024 + ((wm * 8 + i) * 2 + kcl) * 32 + lane];
#pragma unroll
                for (int j = 0; j < 2; j++) {
                    mma_fp16(acc[i][2 * j],     a, b[j].x, b[j].y);
                    mma_fp16(acc[i][2 * j + 1], a, b[j].z, b[j].w);
                }
            }
        }
        cur++;
        if (cur == 3) cur = 0;
    }

    const int d = n0 >> 12;
    const float* bih = d ? bihb : bihf;
    const float* bhh = d ? bhhb : bhhf;
    __half* outd = g_xg + (size_t)d * M_ALL * G4;

#pragma unroll
    for (int jj = 0; jj < 4; jj++) {
        int col = n0 + wn * 32 + jj * 8 + 2 * t4;
        int g = col & (G4 - 1);
        float bx = bih[g] + bhh[g];
        float by = bih[g + 1] + bhh[g + 1];
#pragma unroll
        for (int i = 0; i < 8; i++) {
            int row0 = m0 + wm * 128 + i * 16 + gID;
            __half2 v0 = __floats2half2_rn(acc[i][jj][0] + bx, acc[i][jj][1] + by);
            __half2 v1 = __floats2half2_rn(acc[i][jj][2] + bx, acc[i][jj][3] + by);
            *(__half2*)&outd[(size_t)row0 * G4 + g] = v0;
            *(__half2*)&outd[(size_t)(row0 + 8) * G4 + g] = v1;
        }
    }
}

// ---------------------------------------------------------------------------
// Persistent recurrence kernel (exact R10).
// Warp = (mw = gate, kh = k-parity); warp kh owns kc = 2i + kh, i=0..31.
// ---------------------------------------------------------------------------
__global__ __launch_bounds__(THREADS, 1)
void lstm_persistent(const float* __restrict__ Whhf,
                     const float* __restrict__ Whhb,
                     const float* __restrict__ c0f,
                     const float* __restrict__ c0b,
                     float* __restrict__ out) {
    extern __shared__ char smem[];
    uint4*  Wf = (uint4*)smem;                       // prologue staging only
    __half* Hs = (__half*)(smem + SMEM_W);
    float*  Gs0 = (float*)(smem + SMEM_G0);
    float*  Gs1 = (float*)(smem + SMEM_G1);

    const int tid = threadIdx.x;
    const int d = blockIdx.x >> 6;
    const int s = blockIdx.x & 63;
    const int j0 = s * 16;
    const float* Whh = d ? Whhb : Whhf;

    // ---- prepack W slice into fp16 fragment layout (smem, prologue) ----
    for (int s0 = tid; s0 < 4 * 64 * 32; s0 += THREADS) {
        int l  = s0 & 31;
        int kc = (s0 >> 5) & 63;
        int mw = s0 >> 11;
        int r  = l >> 2;
        int t4 = l & 3;
        int row0 = mw * H + j0 + r;
        int row1 = row0 + 8;
        int k0 = kc * 16 + 2 * t4;
        float2 f0 = *(const float2*)&Whh[(size_t)row0 * H + k0];
        float2 f1 = *(const float2*)&Whh[(size_t)row1 * H + k0];
        float2 f2 = *(const float2*)&Whh[(size_t)row0 * H + k0 + 8];
        float2 f3 = *(const float2*)&Whh[(size_t)row1 * H + k0 + 8];
        __half2 h0 = __float22half2_rn(f0);
        __half2 h1 = __float22half2_rn(f1);
        __half2 h2 = __float22half2_rn(f2);
        __half2 h3 = __float22half2_rn(f3);
        uint4 v;
        v.x = *(unsigned*)&h0; v.y = *(unsigned*)&h1;
        v.z = *(unsigned*)&h2; v.w = *(unsigned*)&h3;
        Wf[s0] = v;
    }
    __syncthreads();

    const int warp = tid >> 5;
    const int lane = tid & 31;
    const int mw = warp & 3;            // gate / m16 tile
    const int kh = warp >> 2;           // k-parity 0/1
    const int gID = lane >> 2;
    const int t4 = lane & 3;

    // ---- W k-chunks into registers: wreg[i] = kc (2i + kh) ----
    const uint4* wfrag = Wf + mw * 2048 + kh * 32 + lane;
    uint4 wreg[32];
#pragma unroll
    for (int i = 0; i < 32; i++) wreg[i] = wfrag[i * 64];

    const __half* hp0 = &Hs[(0 * 8 + gID) * HS_PITCH + 2 * t4];
    const __half* hp1 = &Hs[(1 * 8 + gID) * HS_PITCH + 2 * t4];
    const __half* hp2 = &Hs[(2 * 8 + gID) * HS_PITCH + 2 * t4];
    const __half* hp3 = &Hs[(3 * 8 + gID) * HS_PITCH + 2 * t4];
    float* Gw = kh ? Gs1 : Gs0;

    float c_reg[2];
#pragma unroll
    for (int rep = 0; rep < 2; rep++) {
        int id = tid + rep * 256;
        int jj = id & 15;
        int b = id >> 4;
        c_reg[rep] = (d ? c0b : c0f)[b * H + j0 + jj];
    }

    const size_t xg_dir = (size_t)d * M_ALL * G4;

    float xi[2][4];
    {
        int te0 = d ? (T - 1) : 0;
#pragma unroll
        for (int rep = 0; rep < 2; rep++) {
            int id = tid + rep * 256;
            int jj = id & 15;
            int b = id >> 4;
            const __half* xgp = g_xg + xg_dir
                              + (size_t)(te0 * B + b) * G4 + j0 + jj;
            xi[rep][0] = __half2float(__ldcg(xgp));
            xi[rep][1] = __half2float(__ldcg(xgp + H));
            xi[rep][2] = __half2float(__ldcg(xgp + 2 * H));
            xi[rep][3] = __half2float(__ldcg(xgp + 3 * H));
        }
    }

    float a0[4], a1[4], a2[4], a3[4];

// mma over i in [I0, I1): kc = 2i + kh
#define MMA_RANGE(I0, I1) do {                                             \
    _Pragma("unroll")                                                      \
    for (int i = (I0); i < (I1); i++) {                                    \
        int koff = (2 * i + kh) * 16;                                      \
        unsigned b00 = *(const unsigned*)(hp0 + koff);                     \
        unsigned b01 = *(const unsigned*)(hp0 + koff + 8);                 \
        mma_fp16(a0, wreg[i], b00, b01);                                   \
        unsigned b10 = *(const unsigned*)(hp1 + koff);                     \
        unsigned b11 = *(const unsigned*)(hp1 + koff + 8);                 \
        mma_fp16(a1, wreg[i], b10, b11);                                   \
        unsigned b20 = *(const unsigned*)(hp2 + koff);                     \
        unsigned b21 = *(const unsigned*)(hp2 + koff + 8);                 \
        mma_fp16(a2, wreg[i], b20, b21);                                   \
        unsigned b30 = *(const unsigned*)(hp3 + koff);                     \
        unsigned b31 = *(const unsigned*)(hp3 + koff + 8);                 \
        mma_fp16(a3, wreg[i], b30, b31);                                   \
    }                                                                      \
} while (0)

    for (int t = 0; t < T; t++) {
        const int p = t & 1;
        const int t_eff = d ? (T - 1 - t) : t;
        const uint4* src = (const uint4*)&g_hstage[p][d][0][0];

        // ---- stage h in two k-halves (cols 0..63, then 64..127) ----
#pragma unroll
        for (int i = 0; i < 8; i++) {
            int j = tid + i * 256;
            int b = j >> 6, q = j & 63;
            unsigned dst = (unsigned)__cvta_generic_to_shared(
                &Hs[b * HS_PITCH + q * 8]);
            CP_ASYNC16(dst, src + b * 128 + q);
        }
        CP_COMMIT();
#pragma unroll
        for (int i = 0; i < 8; i++) {
            int j = tid + i * 256;
            int b = j >> 6, q = (j & 63) + 64;
            unsigned dst = (unsigned)__cvta_generic_to_shared(
                &Hs[b * HS_PITCH + q * 8]);
            CP_ASYNC16(dst, src + b * 128 + q);
        }
        CP_COMMIT();

#pragma unroll
        for (int q = 0; q < 4; q++) { a0[q] = a1[q] = a2[q] = a3[q] = 0.f; }

        // ---- mma on half 0 while half 1's latency drains ----
        CP_WAIT1();
        __syncthreads();
        MMA_RANGE(0, 16);

        CP_WAIT0();
        __syncthreads();
        MMA_RANGE(16, 32);

        // ---- stage gate pre-activations (per k-parity buffer) ----
        {
            int row = mw * 16 + gID;
            int cb = 2 * t4;
            float* r0 = Gw + row * 33;
            float* r1 = Gw + (row + 8) * 33;
            r0[cb]      = a0[0]; r0[cb + 1]  = a0[1];
            r1[cb]      = a0[2]; r1[cb + 1]  = a0[3];
            r0[cb + 8]  = a1[0]; r0[cb + 9]  = a1[1];
            r1[cb + 8]  = a1[2]; r1[cb + 9]  = a1[3];
            r0[cb + 16] = a2[0]; r0[cb + 17] = a2[1];
            r1[cb + 16] = a2[2]; r1[cb + 17] = a2[3];
            r0[cb + 24] = a3[0]; r0[cb + 25] = a3[1];
            r1[cb + 24] = a3[2]; r1[cb + 25] = a3[3];
        }
        __syncthreads();

        // ---- pointwise cell update ----
        float hn_keep[2];
#pragma unroll
        for (int rep = 0; rep < 2; rep++) {
            int id = tid + rep * 256;
            int jj = id & 15;
            int b = id >> 4;
            float ig = Gs0[(0  + jj) * 33 + b] + Gs1[(0  + jj) * 33 + b] + xi[rep][0];
            float fg = Gs0[(16 + jj) * 33 + b] + Gs1[(16 + jj) * 33 + b] + xi[rep][1];
            float gg = Gs0[(32 + jj) * 33 + b] + Gs1[(32 + jj) * 33 + b] + xi[rep][2];
            float og = Gs0[(48 + jj) * 33 + b] + Gs1[(48 + jj) * 33 + b] + xi[rep][3];
            ig = sig_(ig);
            fg = sig_(fg);
            og = sig_(og);
            gg = tanh_(gg);
            float cn = fg * c_reg[rep] + ig * gg;
            c_reg[rep] = cn;
            float hn = og * tanh_(cn);
            hn_keep[rep] = hn;
            g_hstage[p ^ 1][d][b][j0 + jj] = __float2half(hn);
        }

        __syncthreads();    // hstage writes done CTA-wide before release

        if (t + 1 < T && tid == 0) red_release_add(&g_bar[d]);

        // hidden behind the barrier: out store + next xg prefetch
#pragma unroll
        for (int rep = 0; rep < 2; rep++) {
            int id = tid + rep * 256;
            int jj = id & 15;
            int b = id >> 4;
            out[(size_t)t_eff * B * OUT_COLS + (size_t)b * OUT_COLS
                + (size_t)d * H + j0 + jj] = hn_keep[rep];
        }
        if (t + 1 < T) {
            int ten = d ? (T - 2 - t) : (t + 1);
#pragma unroll
            for (int rep = 0; rep < 2; rep++) {
                int id = tid + rep * 256;
                int jj = id & 15;
                int b = id >> 4;
                const __half* xgp = g_xg + xg_dir
                                  + (size_t)(ten * B + b) * G4 + j0 + jj;
                xi[rep][0] = __half2float(__ldcg(xgp));
                xi[rep][1] = __half2float(__ldcg(xgp + H));
                xi[rep][2] = __half2float(__ldcg(xgp + 2 * H));
                xi[rep][3] = __half2float(__ldcg(xgp + 3 * H));
            }
            if (tid == 0) {
                unsigned tgt = (unsigned)CTAS_PER_DIR * (t + 1);
                while (ld_acquire(&g_bar[d]) < tgt) { }
            }
            __syncthreads();
        }
    }

#pragma unroll
    for (int rep = 0; rep < 2; rep++) {
        int id = tid + rep * 256;
        int jj = id & 15;
        int b = id >> 4;
        g_c[(size_t)d * B * H + (size_t)b * H + j0 + jj] = c_reg[rep];
    }
}

// ---------------------------------------------------------------------------
__global__ void finalize_kernel(float* __restrict__ out) {
    int i = blockIdx.x * blockDim.x + threadIdx.x;
    if (i >= B * H) return;
    int b = i >> 10;
    int j = i & (H - 1);
    float* tail = out + OUT_MAIN;
    tail[i]             = out[(size_t)(T - 1) * B * OUT_COLS + (size_t)b * OUT_COLS + j];
    tail[B * H + i]     = g_c[i];
    tail[2 * B * H + i] = out[(size_t)b * OUT_COLS + H + j];
    tail[3 * B * H + i] = g_c[B * H + i];
}

// ---------------------------------------------------------------------------
extern "C" void kernel_launch(void* const* d_in, const int* in_sizes, int n_in,
                              void* d_out, int out_size) {
    const float* x    = (const float*)d_in[0];
    const float* h0f  = (const float*)d_in[1];
    const float* c0f  = (const float*)d_in[2];
    const float* h0b  = (const float*)d_in[3];
    const float* c0b  = (const float*)d_in[4];
    const float* Wihf = (const float*)d_in[5];
    const float* Whhf = (const float*)d_in[6];
    const float* bihf = (const float*)d_in[7];
    const float* bhhf = (const float*)d_in[8];
    const float* Wihb = (const float*)d_in[9];
    const float* Whhb = (const float*)d_in[10];
    const float* bihb = (const float*)d_in[11];
    const float* bhhb = (const float*)d_in[12];
    float* out = (float*)d_out;

    static int smem_set = 0;
    if (!smem_set) {
        cudaFuncSetAttribute(lstm_persistent,
                             cudaFuncAttributeMaxDynamicSharedMemorySize,
                             SMEM_BYTES);
        cudaFuncSetAttribute(xg_gemm_hmma,
                             cudaFuncAttributeMaxDynamicSharedMemorySize,
                             GEMM_SMEM);
        smem_set = 1;
    }

    prepack_x<<<(M16 * KC * 32 + 255) / 256, 256>>>(x, h0f, h0b);
    prepack_w<<<(N16 * KC * 32 + 255) / 256, 256>>>(Wihf, Wihb);

    dim3 grid_xg(N_ALL / 64, M_ALL / 256);   // (128, 64)
    xg_gemm_hmma<<<grid_xg, 128, GEMM_SMEM>>>(bihf, bhhf, bihb, bhhb);

    lstm_persistent<<<CTAS, THREADS, SMEM_BYTES>>>(Whhf, Whhb, c0f, c0b, out);

    finalize_kernel<<<(B * H + 255) / 256, 256>>>(out);
}